// round 6
// baseline (speedup 1.0000x reference)
#include <cuda_runtime.h>
#include <cstdint>
#include <math.h>

// BinaryTreeLatentVariable: N_LEAVES=1024, L=16, C=4.
// out[node,o] = parent[node,o] + mL + mR
//             + log( sum_{i,j} expT[o,i,j] * exp(L[i]-mL) * exp(R[j]-mR) )
// Persistent kernel: 256 CTAs, grid barrier between the 10 levels.
// ET duplicated-pair layout in smem -> MOV-free FFMA2 mainloop.

#define OC 64
#define OG 32          // o-groups; each CTA owns 2 outputs
#define XS 8           // node slices
#define NCTA (OG * XS) // 256

__device__ float4 g_ETd[OC * 64 * 32];   // 2 MB: (e,e,e',e') per (o,i,jpair)
__device__ float  g_bufA[512 * OC];
__device__ float  g_bufB[512 * OC];
__device__ unsigned int g_bar;

// ---- packed f32x2 helpers (Blackwell FFMA2) --------------------------------
__device__ __forceinline__ void unpack2(unsigned long long v, float& x, float& y) {
    asm("mov.b64 {%0, %1}, %2;" : "=f"(x), "=f"(y) : "l"(v));
}
__device__ __forceinline__ void ffma2(unsigned long long& d,
                                      unsigned long long a, unsigned long long b) {
    asm("fma.rn.f32x2 %0, %1, %2, %0;" : "+l"(d) : "l"(a), "l"(b));
}

// ---- Prologue: duplicated exp(trans); also reset the grid barrier ----------
__global__ void expT_kernel(const float* __restrict__ trans) {
    if (blockIdx.x == 0 && threadIdx.x == 0) g_bar = 0u;
    int idx = blockIdx.x * 256 + threadIdx.x;   // 0 .. 131071  (o,i,p)
    int o = idx >> 11, i = (idx >> 5) & 63, p = idx & 31;
    int lp = o >> 2, cp = o & 3;
    int ll = i >> 2, cl = i & 3;
    int j0 = 2 * p, j1 = 2 * p + 1;
    int lr0 = j0 >> 2, cr0 = j0 & 3;
    int lr1 = j1 >> 2, cr1 = j1 & 3;
    int s0 = ((((lp * 16 + ll) * 16 + lr0) * 4 + cp) * 4 + cl) * 4 + cr0;
    int s1 = ((((lp * 16 + ll) * 16 + lr1) * 4 + cp) * 4 + cl) * 4 + cr1;
    float e0 = expf(trans[s0]);
    float e1 = expf(trans[s1]);
    g_ETd[idx] = make_float4(e0, e0, e1, e1);
}

// ---------------------------------------------------------------------------
// One chunk of NBX nodes. 8 warps: warp w -> output g=w>>2 (of the CTA's 2),
// i-quarter q=w&3 (16 i's). Lane owns j = {2*lane, 2*lane+1}.
// ---------------------------------------------------------------------------
template <int NBX>
__device__ __forceinline__ void do_chunk(
    int nodeBase, int nend,
    const float* __restrict__ child, const float* __restrict__ parent,
    float* __restrict__ out,
    const float* ETd_s, float* eLs, float* eRs, float* base_s, float* part,
    int og, int warp, int lane, int g, int q)
{
    constexpr int NP = NBX / 2;
    const int tid = warp * 32 + lane;

    __syncthreads();   // smem reuse fence vs previous chunk's epilogue

    // ---- children: batch all loads first (MLP=8), then reduce/exp/store ----
    {
        float l0[2], l1[2], r0[2], r1[2];
        int   nodes[2];
        #pragma unroll
        for (int k = 0; k < 2; k++) {
            const int nb = warp + k * 8;
            nodes[k] = (nb < NBX) ? (nodeBase + nb) : nend;   // sentinel
            if (nb < NBX && nodes[k] < nend) {
                const float* L = child + (size_t)(2 * nodes[k]) * OC;
                l0[k] = L[lane];       l1[k] = L[lane + 32];
                r0[k] = L[lane + 64];  r1[k] = L[lane + 96];
            } else { l0[k] = 0.f; l1[k] = 0.f; r0[k] = 0.f; r1[k] = 0.f; }
        }
        #pragma unroll
        for (int k = 0; k < 2; k++) {
            const int nb = warp + k * 8;
            if (nb >= NBX) break;
            if (nodes[k] < nend) {
                float mL = fmaxf(l0[k], l1[k]), mR = fmaxf(r0[k], r1[k]);
                #pragma unroll
                for (int s = 16; s > 0; s >>= 1) {
                    mL = fmaxf(mL, __shfl_xor_sync(0xffffffffu, mL, s));
                    mR = fmaxf(mR, __shfl_xor_sync(0xffffffffu, mR, s));
                }
                eLs[lane * NBX + nb]        = __expf(l0[k] - mL);
                eLs[(lane + 32) * NBX + nb] = __expf(l1[k] - mL);
                eRs[nb * 64 + lane]         = __expf(r0[k] - mR);
                eRs[nb * 64 + lane + 32]    = __expf(r1[k] - mR);
                if (lane == 0) base_s[nb] = mL + mR;
            } else {
                eLs[lane * NBX + nb] = 0.0f;  eLs[(lane + 32) * NBX + nb] = 0.0f;
                eRs[nb * 64 + lane]  = 0.0f;  eRs[nb * 64 + lane + 32]    = 0.0f;
                if (lane == 0) base_s[nb] = 0.0f;
            }
        }
    }
    __syncthreads();

    // ---- mainloop: per i = 1 LDS.128 (dup ET) + NBX/4 LDS.128 (eL) + FFMA2 ----
    unsigned long long A0[NP], A1[NP];
    #pragma unroll
    for (int p = 0; p < NP; p++) { A0[p] = 0ull; A1[p] = 0ull; }

    const ulonglong2* etd =
        reinterpret_cast<const ulonglong2*>(ETd_s + (size_t)g * 8192);
    const int ib = q * 16;
    #pragma unroll
    for (int ii = 0; ii < 16; ii++) {
        const int i = ib + ii;
        ulonglong2 e = etd[i * 32 + lane];   // e.x=(ex,ex)  e.y=(ey,ey)
        const ulonglong2* el2 = reinterpret_cast<const ulonglong2*>(eLs + i * NBX);
        #pragma unroll
        for (int pp = 0; pp < NBX / 4; pp++) {
            ulonglong2 w = el2[pp];          // 4 nodes, one LDS.128 broadcast
            ffma2(A0[2 * pp],     e.x, w.x);
            ffma2(A1[2 * pp],     e.y, w.x);
            ffma2(A0[2 * pp + 1], e.x, w.y);
            ffma2(A1[2 * pp + 1], e.y, w.y);
        }
    }

    // ---- fold eR, warp-reduce, stash quarter-partials ----
    #pragma unroll
    for (int p = 0; p < NP; p++) {
        float a0x, a0y, a1x, a1y;
        unpack2(A0[p], a0x, a0y);
        unpack2(A1[p], a1x, a1y);
        #pragma unroll
        for (int h = 0; h < 2; h++) {
            const int nb = 2 * p + h;
            const float aj0 = h ? a0y : a0x;
            const float aj1 = h ? a1y : a1x;
            float2 er = reinterpret_cast<const float2*>(eRs + nb * 64)[lane];
            float v = aj0 * er.x + aj1 * er.y;
            #pragma unroll
            for (int s = 16; s > 0; s >>= 1)
                v += __shfl_xor_sync(0xffffffffu, v, s);
            if (lane == 0) part[(g * 16 + nb) * 4 + q] = v;
        }
    }
    __syncthreads();

    // ---- epilogue: combine quarters, log, write ----
    if (tid < 2 * NBX) {
        const int gg = tid / NBX, nb = tid % NBX;
        const int node = nodeBase + nb;
        if (node < nend) {
            const float* pr = part + (gg * 16 + nb) * 4;
            float v = (pr[0] + pr[1]) + (pr[2] + pr[3]);
            const int o = og * 2 + gg;
            out[(size_t)node * OC + o] =
                parent[(size_t)node * OC + o] + base_s[nb] + logf(v);
        }
    }
}

// ---------------------------------------------------------------------------
// Persistent tree kernel: all 10 levels, grid barrier between them.
// ---------------------------------------------------------------------------
__global__ __launch_bounds__(256, 2) void tree_kernel(
    const float* __restrict__ node_state, float* __restrict__ d_out)
{
    extern __shared__ float smem[];
    float* ETd_s  = smem;                  // 2 o * 8192 floats = 64 KB
    float* eLs    = smem + 16384;          // [i][nb]  64*16
    float* eRs    = eLs + 64 * 16;         // [nb][j]  16*64
    float* base_s = eRs + 16 * 64;         // 16
    float* part   = base_s + 16;           // [g][nb][q]  2*16*4

    const int tid  = threadIdx.x;
    const int warp = tid >> 5;
    const int lane = tid & 31;
    const int og   = blockIdx.x & (OG - 1);
    const int xs   = blockIdx.x >> 5;      // 0..7
    const int g    = warp >> 2;            // output within CTA's pair
    const int q    = warp & 3;             // i-quarter

    // ---- one-time ETd slice fill: 64 KB via cp.async ----
    {
        unsigned int dst;
        asm("{ .reg .u64 t; cvta.to.shared.u64 t, %1; cvt.u32.u64 %0, t; }"
            : "=r"(dst) : "l"(ETd_s));
        const float4* src = g_ETd + (size_t)og * 4096;  // 2 o * 2048 float4
        #pragma unroll
        for (int t = 0; t < 16; t++) {
            int e = tid + t * 256;
            asm volatile("cp.async.cg.shared.global [%0], [%1], 16;"
                         :: "r"(dst + 16u * (unsigned)e), "l"(src + e));
        }
        asm volatile("cp.async.commit_group;");
        asm volatile("cp.async.wait_group 0;");
    }
    __syncthreads();

    const float* leaves = node_state + (size_t)1023 * OC;

    #pragma unroll 1
    for (int l = 0; l < 10; l++) {
        const int n = 512 >> l;
        const float* child = (l == 0) ? leaves : ((l & 1) ? g_bufA : g_bufB);
        float* out = (l == 9) ? d_out : ((l & 1) ? g_bufB : g_bufA);
        const float* parent = node_state + (size_t)(n - 1) * OC;

        const int npc    = (n + XS - 1) / XS;
        const int nstart = xs * npc;
        const int nend   = (nstart + npc < n) ? (nstart + npc) : n;

        if (nstart < n) {
            if (npc >= 16) {
                for (int nb0 = nstart; nb0 < nend; nb0 += 16)
                    do_chunk<16>(nb0, nend, child, parent, out,
                                 ETd_s, eLs, eRs, base_s, part,
                                 og, warp, lane, g, q);
            } else if (npc == 8) {
                do_chunk<8>(nstart, nend, child, parent, out,
                            ETd_s, eLs, eRs, base_s, part,
                            og, warp, lane, g, q);
            } else {
                for (int nb0 = nstart; nb0 < nend; nb0 += 4)
                    do_chunk<4>(nb0, nend, child, parent, out,
                                ETd_s, eLs, eRs, base_s, part,
                                og, warp, lane, g, q);
            }
        }

        // ---- grid barrier (except after last level) ----
        if (l < 9) {
            __syncthreads();
            if (tid == 0) {
                __threadfence();
                atomicAdd(&g_bar, 1u);
                const unsigned int tgt = (unsigned int)(l + 1) * NCTA;
                while (*(volatile unsigned int*)&g_bar < tgt) { }
                __threadfence();
            }
            __syncthreads();
        }
    }
}

// ---------------------------------------------------------------------------
// Host side
// ---------------------------------------------------------------------------
#define TREE_SMEM ((16384 + 64 * 16 + 16 * 64 + 16 + 2 * 16 * 4) * 4)

extern "C" void kernel_launch(void* const* d_in, const int* in_sizes, int n_in,
                              void* d_out, int out_size)
{
    const float* node_state = (const float*)d_in[0];
    const float* trans      = (const float*)d_in[1];
    if (n_in >= 2 && in_sizes[0] == 262144) {   // defensive input identification
        const float* t = node_state; node_state = trans; trans = t;
    }

    cudaFuncSetAttribute(tree_kernel,
                         cudaFuncAttributeMaxDynamicSharedMemorySize, TREE_SMEM);

    expT_kernel<<<512, 256>>>(trans);
    tree_kernel<<<NCTA, 256, TREE_SMEM>>>(node_state, (float*)d_out);
}

// round 8
// speedup vs baseline: 1.2209x; 1.2209x over previous
#include <cuda_runtime.h>
#include <cstdint>
#include <math.h>

// BinaryTreeLatentVariable: N_LEAVES=1024, L=16, C=4.
// out[node,o] = parent[node,o] + mL + mR
//             + log( sum_{i,j} expT[o,i,j] * exp(L[i]-mL) * exp(R[j]-mR) )
// Persistent kernel: 256 CTAs, grid barrier between levels.
// R8: shfl reductions (redux.f32 not on sm_100), eLs stride-20 (4-way vs
// 16-way STS conflicts), child-LDG prefetch pipeline, double-buffered chunk
// smem, release/acquire grid barrier.

#define OC 64
#define OG 32          // o-groups; each CTA owns 2 outputs
#define XS 8           // node slices
#define NCTA (OG * XS) // 256
#define ELS 20         // eLs row stride (floats): 16B-aligned, gcd(20,32)=4

__device__ float g_ET[OC * 4096];    // 1 MB: exp(trans) repacked [o][i][j]
__device__ float g_bufA[512 * OC];
__device__ float g_bufB[512 * OC];
__device__ unsigned int g_bar;

// ---- packed f32x2 helpers (FFMA2) ------------------------------------------
__device__ __forceinline__ unsigned long long pack2(float x, float y) {
    unsigned long long r;
    asm("mov.b64 %0, {%1, %2};" : "=l"(r) : "f"(x), "f"(y));
    return r;
}
__device__ __forceinline__ void unpack2(unsigned long long v, float& x, float& y) {
    asm("mov.b64 {%0, %1}, %2;" : "=f"(x), "=f"(y) : "l"(v));
}
__device__ __forceinline__ void ffma2(unsigned long long& d,
                                      unsigned long long a, unsigned long long b) {
    asm("fma.rn.f32x2 %0, %1, %2, %0;" : "+l"(d) : "l"(a), "l"(b));
}
__device__ __forceinline__ float warp_sum(float v) {
    #pragma unroll
    for (int s = 16; s > 0; s >>= 1)
        v += __shfl_xor_sync(0xffffffffu, v, s);
    return v;
}
__device__ __forceinline__ float warp_max(float v) {
    #pragma unroll
    for (int s = 16; s > 0; s >>= 1)
        v = fmaxf(v, __shfl_xor_sync(0xffffffffu, v, s));
    return v;
}

// ---- Prologue: ET[o][i][j] = exp(trans[...]); reset grid barrier -----------
__global__ void expT_kernel(const float* __restrict__ trans) {
    if (blockIdx.x == 0 && threadIdx.x == 0) g_bar = 0u;
    int idx = blockIdx.x * 256 + threadIdx.x;   // 0 .. 262143
    int o = idx >> 12, i = (idx >> 6) & 63, j = idx & 63;
    int lp = o >> 2, cp = o & 3;
    int ll = i >> 2, cl = i & 3;
    int lr = j >> 2, cr = j & 3;
    int src = ((((lp * 16 + ll) * 16 + lr) * 4 + cp) * 4 + cl) * 4 + cr;
    g_ET[idx] = expf(trans[src]);
}

// ---- child prefetch: issue 8 LDGs for one chunk's 2 nodes/warp -------------
template <int NBX>
__device__ __forceinline__ void prefetch_children(
    float* P, int nodeBase, int nend,
    const float* __restrict__ child, int warp, int lane)
{
    #pragma unroll
    for (int k = 0; k < 2; k++) {
        const int nb = warp + k * 8;
        const int node = nodeBase + nb;
        if (nb < NBX && node < nend) {
            const float* L = child + (size_t)(2 * node) * OC;
            P[4 * k + 0] = L[lane];       P[4 * k + 1] = L[lane + 32];
            P[4 * k + 2] = L[lane + 64];  P[4 * k + 3] = L[lane + 96];
        }
    }
}

// ---------------------------------------------------------------------------
// One chunk of NBX nodes. 8 warps: warp w -> output g=w>>2 (of the CTA's 2),
// i-quarter q=w&3 (16 i's). Lane owns j = {2*lane, 2*lane+1}.
// P holds this chunk's prefetched children; on exit it holds the next chunk's.
// ---------------------------------------------------------------------------
template <int NBX>
__device__ __forceinline__ void do_chunk(
    int nodeBase, int nend,
    const float* __restrict__ child, const float* __restrict__ parent,
    float* __restrict__ out,
    const float* ET_s, float* eLs, float* eRs, float* base_s, float* part,
    float* P, int cb, int og, int warp, int lane, int g, int q)
{
    constexpr int NP = NBX / 2;
    const int tid = warp * 32 + lane;

    float* eLb   = eLs    + cb * (64 * ELS);
    float* eRb   = eRs    + cb * 1024;
    float* baseb = base_s + cb * 16;
    float* partb = part   + cb * 128;

    // ---- consume prefetched children: max -> exp -> smem ----
    #pragma unroll
    for (int k = 0; k < 2; k++) {
        const int nb = warp + k * 8;
        if (nb >= NBX) break;
        const int node = nodeBase + nb;
        if (node < nend) {
            float mL = warp_max(fmaxf(P[4 * k + 0], P[4 * k + 1]));
            float mR = warp_max(fmaxf(P[4 * k + 2], P[4 * k + 3]));
            eLb[lane * ELS + nb]        = __expf(P[4 * k + 0] - mL);
            eLb[(lane + 32) * ELS + nb] = __expf(P[4 * k + 1] - mL);
            eRb[nb * 64 + lane]         = __expf(P[4 * k + 2] - mR);
            eRb[nb * 64 + lane + 32]    = __expf(P[4 * k + 3] - mR);
            if (lane == 0) baseb[nb] = mL + mR;
        } else {
            eLb[lane * ELS + nb] = 0.0f;  eLb[(lane + 32) * ELS + nb] = 0.0f;
            eRb[nb * 64 + lane]  = 0.0f;  eRb[nb * 64 + lane + 32]    = 0.0f;
            if (lane == 0) baseb[nb] = 0.0f;
        }
    }
    __syncthreads();

    // ---- prefetch next chunk (LDG latency hidden under mainloop) ----
    if (nodeBase + NBX < nend)
        prefetch_children<NBX>(P, nodeBase + NBX, nend, child, warp, lane);

    // ---- mainloop: 16 i's, FFMA2 over NBX accumulator pairs ----
    unsigned long long A0[NP], A1[NP];
    #pragma unroll
    for (int p = 0; p < NP; p++) { A0[p] = 0ull; A1[p] = 0ull; }

    const float2* ets = reinterpret_cast<const float2*>(ET_s + (size_t)g * 4096);
    const int ib = q * 16;
    #pragma unroll
    for (int ii = 0; ii < 16; ii++) {
        const int i = ib + ii;
        float2 e = ets[i * 32 + lane];               // ET[o, i, 2lane..+1]
        unsigned long long exx = pack2(e.x, e.x);
        unsigned long long eyy = pack2(e.y, e.y);
        const ulonglong2* el2 = reinterpret_cast<const ulonglong2*>(eLb + i * ELS);
        #pragma unroll
        for (int pp = 0; pp < NBX / 4; pp++) {
            ulonglong2 w = el2[pp];                  // 4 nodes, one LDS.128
            ffma2(A0[2 * pp],     exx, w.x);
            ffma2(A1[2 * pp],     eyy, w.x);
            ffma2(A0[2 * pp + 1], exx, w.y);
            ffma2(A1[2 * pp + 1], eyy, w.y);
        }
    }

    // ---- fold eR, warp-reduce, stash quarter-partials ----
    #pragma unroll
    for (int p = 0; p < NP; p++) {
        float a0x, a0y, a1x, a1y;
        unpack2(A0[p], a0x, a0y);
        unpack2(A1[p], a1x, a1y);
        #pragma unroll
        for (int h = 0; h < 2; h++) {
            const int nb = 2 * p + h;
            const float aj0 = h ? a0y : a0x;
            const float aj1 = h ? a1y : a1x;
            float2 er = reinterpret_cast<const float2*>(eRb + nb * 64)[lane];
            float v = warp_sum(aj0 * er.x + aj1 * er.y);
            if (lane == 0) partb[(g * 16 + nb) * 4 + q] = v;
        }
    }
    __syncthreads();

    // ---- epilogue: combine quarters, log, write ----
    if (tid < 2 * NBX) {
        const int gg = tid / NBX, nb = tid % NBX;
        const int node = nodeBase + nb;
        if (node < nend) {
            const float* pr = partb + (gg * 16 + nb) * 4;
            float v = (pr[0] + pr[1]) + (pr[2] + pr[3]);
            const int o = og * 2 + gg;
            out[(size_t)node * OC + o] =
                parent[(size_t)node * OC + o] + baseb[nb] + __logf(v);
        }
    }
}

// ---------------------------------------------------------------------------
// Persistent tree kernel: all 10 levels, grid barrier between them.
// ---------------------------------------------------------------------------
__global__ __launch_bounds__(256, 2) void tree_kernel(
    const float* __restrict__ node_state, float* __restrict__ d_out)
{
    extern __shared__ float smem[];
    float* ET_s   = smem;                  // 2 o * 4096 = 8192 floats (32 KB)
    float* eLs    = smem + 8192;           // 2 x [64][ELS]
    float* eRs    = eLs + 2 * 64 * ELS;    // 2 x [16][64]
    float* base_s = eRs + 2048;            // 2 x 16
    float* part   = base_s + 32;           // 2 x 128

    const int tid  = threadIdx.x;
    const int warp = tid >> 5;
    const int lane = tid & 31;
    const int og   = blockIdx.x & (OG - 1);
    const int xs   = blockIdx.x >> 5;      // 0..7
    const int g    = warp >> 2;            // output within CTA's pair
    const int q    = warp & 3;             // i-quarter

    // ---- one-time ET slice fill: 32 KB via cp.async ----
    {
        unsigned int dst;
        asm("{ .reg .u64 t; cvta.to.shared.u64 t, %1; cvt.u32.u64 %0, t; }"
            : "=r"(dst) : "l"(ET_s));
        const float4* src = reinterpret_cast<const float4*>(g_ET)
                            + (size_t)og * 2048;
        #pragma unroll
        for (int t = 0; t < 8; t++) {
            int e = tid + t * 256;
            asm volatile("cp.async.cg.shared.global [%0], [%1], 16;"
                         :: "r"(dst + 16u * (unsigned)e), "l"(src + e));
        }
        asm volatile("cp.async.commit_group;");
        asm volatile("cp.async.wait_group 0;");
    }
    __syncthreads();

    const float* leaves = node_state + (size_t)1023 * OC;
    float P[8];

    #pragma unroll 1
    for (int l = 0; l < 10; l++) {
        const int n = 512 >> l;
        const float* child = (l == 0) ? leaves : ((l & 1) ? g_bufA : g_bufB);
        float* out = (l == 9) ? d_out : ((l & 1) ? g_bufB : g_bufA);
        const float* parent = node_state + (size_t)(n - 1) * OC;

        const int npc    = (n + XS - 1) / XS;
        const int nstart = xs * npc;
        const int nend   = (nstart + npc < n) ? (nstart + npc) : n;

        if (nstart < n) {
            if (npc >= 16) {
                prefetch_children<16>(P, nstart, nend, child, warp, lane);
                int cb = 0;
                for (int nb0 = nstart; nb0 < nend; nb0 += 16, cb ^= 1)
                    do_chunk<16>(nb0, nend, child, parent, out,
                                 ET_s, eLs, eRs, base_s, part,
                                 P, cb, og, warp, lane, g, q);
            } else if (npc == 8) {
                prefetch_children<8>(P, nstart, nend, child, warp, lane);
                do_chunk<8>(nstart, nend, child, parent, out,
                            ET_s, eLs, eRs, base_s, part,
                            P, 0, og, warp, lane, g, q);
            } else {
                prefetch_children<4>(P, nstart, nend, child, warp, lane);
                int cb = 0;
                for (int nb0 = nstart; nb0 < nend; nb0 += 4, cb ^= 1)
                    do_chunk<4>(nb0, nend, child, parent, out,
                                ET_s, eLs, eRs, base_s, part,
                                P, cb, og, warp, lane, g, q);
            }
        }

        // ---- grid barrier (release/acquire, except after last level) ----
        if (l < 9) {
            __syncthreads();
            if (tid == 0) {
                asm volatile("red.release.gpu.global.add.u32 [%0], 1;"
                             :: "l"(&g_bar) : "memory");
                const unsigned int tgt = (unsigned int)(l + 1) * NCTA;
                unsigned int cur;
                do {
                    asm volatile("ld.acquire.gpu.global.u32 %0, [%1];"
                                 : "=r"(cur) : "l"(&g_bar) : "memory");
                } while (cur < tgt);
            }
            __syncthreads();
        }
    }
}

// ---------------------------------------------------------------------------
// Host side
// ---------------------------------------------------------------------------
#define TREE_SMEM ((8192 + 2 * 64 * ELS + 2048 + 32 + 256) * 4)

extern "C" void kernel_launch(void* const* d_in, const int* in_sizes, int n_in,
                              void* d_out, int out_size)
{
    const float* node_state = (const float*)d_in[0];
    const float* trans      = (const float*)d_in[1];
    if (n_in >= 2 && in_sizes[0] == 262144) {   // defensive input identification
        const float* t = node_state; node_state = trans; trans = t;
    }

    cudaFuncSetAttribute(tree_kernel,
                         cudaFuncAttributeMaxDynamicSharedMemorySize, TREE_SMEM);

    expT_kernel<<<1024, 256>>>(trans);
    tree_kernel<<<NCTA, 256, TREE_SMEM>>>(node_state, (float*)d_out);
}

// round 9
// speedup vs baseline: 1.4871x; 1.2181x over previous
#include <cuda_runtime.h>
#include <cstdint>
#include <math.h>

// BinaryTreeLatentVariable: N_LEAVES=1024, L=16, C=4.
// out[node,o] = parent[node,o] + mL + mR
//             + log( sum_{i,j} expT[o,i,j] * exp(L[i]-mL) * exp(R[j]-mR) )
// Persistent kernel: 256 CTAs (16 o-groups x 16 node slices), grid barrier
// between levels. R9: CTA owns 4 outputs (warp = (g, i-half), 32 i/warp),
// butterfly multi-value warp reduction (16 SHFL vs 80), parent prefetch.

#define OC 64
#define OG 16          // o-groups; each CTA owns 4 outputs
#define XS 16          // node slices
#define NCTA (OG * XS) // 256
#define ELS 20         // eLs row stride (floats): 16B-aligned, 4-way STS conflicts

__device__ float g_ET[OC * 4096];    // 1 MB: exp(trans) repacked [o][i][j]
__device__ float g_bufA[512 * OC];
__device__ float g_bufB[512 * OC];
__device__ unsigned int g_bar;

// ---- packed f32x2 helpers (FFMA2) ------------------------------------------
__device__ __forceinline__ unsigned long long pack2(float x, float y) {
    unsigned long long r;
    asm("mov.b64 %0, {%1, %2};" : "=l"(r) : "f"(x), "f"(y));
    return r;
}
__device__ __forceinline__ void unpack2(unsigned long long v, float& x, float& y) {
    asm("mov.b64 {%0, %1}, %2;" : "=f"(x), "=f"(y) : "l"(v));
}
__device__ __forceinline__ void ffma2(unsigned long long& d,
                                      unsigned long long a, unsigned long long b) {
    asm("fma.rn.f32x2 %0, %1, %2, %0;" : "+l"(d) : "l"(a), "l"(b));
}
__device__ __forceinline__ float warp_max(float v) {
    #pragma unroll
    for (int s = 16; s > 0; s >>= 1)
        v = fmaxf(v, __shfl_xor_sync(0xffffffffu, v, s));
    return v;
}

// ---- butterfly multi-value warp allreduce ----------------------------------
// NV independent 32-lane sums in ~NV SHFL total. On return each lane holds
// the full sum of value idx(lane); 32/NV lanes duplicate each value.
template <int NV>
__device__ __forceinline__ float butterflyN(float s[NV], int lane) {
    #pragma unroll
    for (int k = 0; k < 5; k++) {
        const int w = 16 >> k;
        const int m = (NV / 2) >> k;
        if (m >= 1) {
            const bool up = (lane & w) != 0;
            #pragma unroll
            for (int i = 0; i < m; i++) {
                float t = up ? s[i] : s[i + m];
                float r = __shfl_xor_sync(0xffffffffu, t, w);
                s[i] = (up ? s[i + m] : s[i]) + r;
            }
        } else {
            s[0] += __shfl_xor_sync(0xffffffffu, s[0], w);
        }
    }
    return s[0];
}
template <int NV>
__device__ __forceinline__ int butterfly_idx(int lane) {
    int idx = 0;
    #pragma unroll
    for (int k = 0; k < 5; k++) {
        const int m = (NV / 2) >> k;
        if (m >= 1) idx += ((lane >> (4 - k)) & 1) * m;
    }
    return idx;
}

// ---- Prologue: ET[o][i][j] = exp(trans[...]); reset grid barrier -----------
__global__ void expT_kernel(const float* __restrict__ trans) {
    if (blockIdx.x == 0 && threadIdx.x == 0) g_bar = 0u;
    int idx = blockIdx.x * 256 + threadIdx.x;   // 0 .. 262143
    int o = idx >> 12, i = (idx >> 6) & 63, j = idx & 63;
    int lp = o >> 2, cp = o & 3;
    int ll = i >> 2, cl = i & 3;
    int lr = j >> 2, cr = j & 3;
    int src = ((((lp * 16 + ll) * 16 + lr) * 4 + cp) * 4 + cl) * 4 + cr;
    g_ET[idx] = expf(trans[src]);
}

// ---- prefetch one chunk's children + parent values -------------------------
template <int NBX>
__device__ __forceinline__ void prefetch_chunk(
    float* P, float& pPar, int nodeBase, int nend,
    const float* __restrict__ child, const float* __restrict__ parent,
    int og, int tid, int warp, int lane)
{
    #pragma unroll
    for (int k = 0; k < 2; k++) {
        const int nb = warp + k * 8;
        const int node = nodeBase + nb;
        if (nb < NBX && node < nend) {
            const float* L = child + (size_t)(2 * node) * OC;
            P[4 * k + 0] = L[lane];       P[4 * k + 1] = L[lane + 32];
            P[4 * k + 2] = L[lane + 64];  P[4 * k + 3] = L[lane + 96];
        }
    }
    if (tid < 4 * NBX) {
        const int nb = tid & (NBX - 1);
        const int node = nodeBase + nb;
        if (node < nend)
            pPar = parent[(size_t)node * OC + og * 4 + tid / NBX];
    }
}

// ---------------------------------------------------------------------------
// One chunk of NBX nodes. 8 warps: warp w -> output g=w>>1 of the CTA's four,
// i-half = w&1 (32 i's). Lane owns j = {2*lane, 2*lane+1}.
// P/pPar hold this chunk's prefetched data; refilled for the next chunk.
// ---------------------------------------------------------------------------
template <int NBX>
__device__ __forceinline__ void do_chunk(
    int nodeBase, int nend, bool last,
    const float* __restrict__ child, const float* __restrict__ parent,
    float* __restrict__ out,
    const float* ET_s, float* eLs, float* eRs, float* base_s, float* part,
    float* P, float& pPar, int cb, int og, int tid, int warp, int lane,
    int g, int half)
{
    constexpr int NP = NBX / 2;
    const float pcur = pPar;

    float* eLb   = eLs    + cb * (64 * ELS);
    float* eRb   = eRs    + cb * 1024;
    float* baseb = base_s + cb * 16;
    float* partb = part   + cb * 128;

    // ---- consume prefetched children: max -> exp -> smem ----
    #pragma unroll
    for (int k = 0; k < 2; k++) {
        const int nb = warp + k * 8;
        if (nb >= NBX) break;
        const int node = nodeBase + nb;
        if (node < nend) {
            float mL = warp_max(fmaxf(P[4 * k + 0], P[4 * k + 1]));
            float mR = warp_max(fmaxf(P[4 * k + 2], P[4 * k + 3]));
            eLb[lane * ELS + nb]        = __expf(P[4 * k + 0] - mL);
            eLb[(lane + 32) * ELS + nb] = __expf(P[4 * k + 1] - mL);
            eRb[nb * 64 + lane]         = __expf(P[4 * k + 2] - mR);
            eRb[nb * 64 + lane + 32]    = __expf(P[4 * k + 3] - mR);
            if (lane == 0) baseb[nb] = mL + mR;
        } else {
            eLb[lane * ELS + nb] = 0.0f;  eLb[(lane + 32) * ELS + nb] = 0.0f;
            eRb[nb * 64 + lane]  = 0.0f;  eRb[nb * 64 + lane + 32]    = 0.0f;
            if (lane == 0) baseb[nb] = 0.0f;
        }
    }
    __syncthreads();

    // ---- prefetch next chunk (LDG latency hidden under mainloop) ----
    if (!last)
        prefetch_chunk<NBX>(P, pPar, nodeBase + NBX, nend, child, parent,
                            og, tid, warp, lane);

    // ---- mainloop: 32 i's, FFMA2 over NBX accumulator pairs ----
    unsigned long long A0[NP], A1[NP];
    #pragma unroll
    for (int p = 0; p < NP; p++) { A0[p] = 0ull; A1[p] = 0ull; }

    const float2* ets = reinterpret_cast<const float2*>(ET_s + (size_t)g * 4096);
    const int ib = half * 32;
    #pragma unroll 8
    for (int ii = 0; ii < 32; ii++) {
        const int i = ib + ii;
        float2 e = ets[i * 32 + lane];               // ET[o, i, 2lane..+1]
        unsigned long long exx = pack2(e.x, e.x);
        unsigned long long eyy = pack2(e.y, e.y);
        const ulonglong2* el2 = reinterpret_cast<const ulonglong2*>(eLb + i * ELS);
        #pragma unroll
        for (int pp = 0; pp < NBX / 4; pp++) {
            ulonglong2 w = el2[pp];                  // 4 nodes, one LDS.128
            ffma2(A0[2 * pp],     exx, w.x);
            ffma2(A1[2 * pp],     eyy, w.x);
            ffma2(A0[2 * pp + 1], exx, w.y);
            ffma2(A1[2 * pp + 1], eyy, w.y);
        }
    }

    // ---- fold eR, butterfly-reduce NBX sums, one predicated STS ----
    float s[NBX];
    #pragma unroll
    for (int p = 0; p < NP; p++) {
        float a0x, a0y, a1x, a1y;
        unpack2(A0[p], a0x, a0y);
        unpack2(A1[p], a1x, a1y);
        float2 er0 = reinterpret_cast<const float2*>(eRb + (2 * p) * 64)[lane];
        float2 er1 = reinterpret_cast<const float2*>(eRb + (2 * p + 1) * 64)[lane];
        s[2 * p]     = a0x * er0.x + a1x * er0.y;
        s[2 * p + 1] = a0y * er1.x + a1y * er1.y;
    }
    float v = butterflyN<NBX>(s, lane);
    const int idx = butterfly_idx<NBX>(lane);
    if ((lane & (32 / NBX - 1)) == 0)
        partb[(g * NBX + idx) * 2 + half] = v;
    __syncthreads();

    // ---- epilogue: combine halves, log, write (parent prefetched) ----
    if (tid < 4 * NBX) {
        const int gg = tid / NBX, nb = tid & (NBX - 1);
        const int node = nodeBase + nb;
        if (node < nend) {
            float vv = partb[(gg * NBX + nb) * 2] + partb[(gg * NBX + nb) * 2 + 1];
            out[(size_t)node * OC + og * 4 + gg] = pcur + baseb[nb] + __logf(vv);
        }
    }
}

// ---------------------------------------------------------------------------
// Persistent tree kernel: all 10 levels, grid barrier between them.
// ---------------------------------------------------------------------------
__global__ __launch_bounds__(256, 2) void tree_kernel(
    const float* __restrict__ node_state, float* __restrict__ d_out)
{
    extern __shared__ float smem[];
    float* ET_s   = smem;                  // 4 o * 4096 = 16384 floats (64 KB)
    float* eLs    = smem + 16384;          // 2 x [64][ELS]
    float* eRs    = eLs + 2 * 64 * ELS;    // 2 x [16][64]
    float* base_s = eRs + 2048;            // 2 x 16
    float* part   = base_s + 32;           // 2 x [g][nb][half] = 2 x 128

    const int tid  = threadIdx.x;
    const int warp = tid >> 5;
    const int lane = tid & 31;
    const int og   = blockIdx.x & (OG - 1);
    const int xs   = blockIdx.x >> 4;      // 0..15
    const int g    = warp >> 1;            // output within CTA's four
    const int half = warp & 1;             // i-half

    // ---- one-time ET slice fill: 64 KB via cp.async ----
    {
        unsigned int dst;
        asm("{ .reg .u64 t; cvta.to.shared.u64 t, %1; cvt.u32.u64 %0, t; }"
            : "=r"(dst) : "l"(ET_s));
        const float4* src = reinterpret_cast<const float4*>(g_ET)
                            + (size_t)og * 4096;
        #pragma unroll
        for (int t = 0; t < 16; t++) {
            int e = tid + t * 256;
            asm volatile("cp.async.cg.shared.global [%0], [%1], 16;"
                         :: "r"(dst + 16u * (unsigned)e), "l"(src + e));
        }
        asm volatile("cp.async.commit_group;");
        asm volatile("cp.async.wait_group 0;");
    }
    __syncthreads();

    const float* leaves = node_state + (size_t)1023 * OC;
    float P[8];
    float pPar = 0.0f;

    #pragma unroll 1
    for (int l = 0; l < 10; l++) {
        const int n = 512 >> l;
        const float* child = (l == 0) ? leaves : ((l & 1) ? g_bufA : g_bufB);
        float* out = (l == 9) ? d_out : ((l & 1) ? g_bufB : g_bufA);
        const float* parent = node_state + (size_t)(n - 1) * OC;

        const int npc    = (n + XS - 1) / XS;
        const int nstart = xs * npc;
        const int nend   = (nstart + npc < n) ? (nstart + npc) : n;

        if (nstart < n) {
            if (npc >= 16) {
                prefetch_chunk<16>(P, pPar, nstart, nend, child, parent,
                                   og, tid, warp, lane);
                int cb = 0;
                for (int nb0 = nstart; nb0 < nend; nb0 += 16, cb ^= 1)
                    do_chunk<16>(nb0, nend, nb0 + 16 >= nend, child, parent, out,
                                 ET_s, eLs, eRs, base_s, part,
                                 P, pPar, cb, og, tid, warp, lane, g, half);
            } else if (npc == 8) {
                prefetch_chunk<8>(P, pPar, nstart, nend, child, parent,
                                  og, tid, warp, lane);
                do_chunk<8>(nstart, nend, true, child, parent, out,
                            ET_s, eLs, eRs, base_s, part,
                            P, pPar, 0, og, tid, warp, lane, g, half);
            } else {
                prefetch_chunk<4>(P, pPar, nstart, nend, child, parent,
                                  og, tid, warp, lane);
                int cb = 0;
                for (int nb0 = nstart; nb0 < nend; nb0 += 4, cb ^= 1)
                    do_chunk<4>(nb0, nend, nb0 + 4 >= nend, child, parent, out,
                                ET_s, eLs, eRs, base_s, part,
                                P, pPar, cb, og, tid, warp, lane, g, half);
            }
        }

        // ---- grid barrier (release/acquire, except after last level) ----
        if (l < 9) {
            __syncthreads();
            if (tid == 0) {
                asm volatile("red.release.gpu.global.add.u32 [%0], 1;"
                             :: "l"(&g_bar) : "memory");
                const unsigned int tgt = (unsigned int)(l + 1) * NCTA;
                unsigned int cur;
                do {
                    asm volatile("ld.acquire.gpu.global.u32 %0, [%1];"
                                 : "=r"(cur) : "l"(&g_bar) : "memory");
                } while (cur < tgt);
            }
            __syncthreads();
        }
    }
}

// ---------------------------------------------------------------------------
// Host side
// ---------------------------------------------------------------------------
#define TREE_SMEM ((16384 + 2 * 64 * ELS + 2048 + 32 + 256) * 4)

extern "C" void kernel_launch(void* const* d_in, const int* in_sizes, int n_in,
                              void* d_out, int out_size)
{
    const float* node_state = (const float*)d_in[0];
    const float* trans      = (const float*)d_in[1];
    if (n_in >= 2 && in_sizes[0] == 262144) {   // defensive input identification
        const float* t = node_state; node_state = trans; trans = t;
    }

    cudaFuncSetAttribute(tree_kernel,
                         cudaFuncAttributeMaxDynamicSharedMemorySize, TREE_SMEM);

    expT_kernel<<<1024, 256>>>(trans);
    tree_kernel<<<NCTA, 256, TREE_SMEM>>>(node_state, (float*)d_out);
}